// round 15
// baseline (speedup 1.0000x reference)
#include <cuda_runtime.h>
#include <math.h>

#define BB 8
#define CC 32
#define SS 256
#define HP 288
#define KY 12
#define MM 24
#define NLAY 4
#define PLANE (HP*HP)

typedef unsigned long long ull;

// ---------------- packed f32x2 helpers ----------------
__device__ __forceinline__ ull pk(float lo, float hi) {
    ull r; asm("mov.b64 %0,{%1,%2};" : "=l"(r) : "f"(lo), "f"(hi)); return r;
}
__device__ __forceinline__ ull dup2(float v) { return pk(v, v); }
__device__ __forceinline__ void upk(float& lo, float& hi, ull v) {
    asm("mov.b64 {%0,%1},%2;" : "=f"(lo), "=f"(hi) : "l"(v));
}
__device__ __forceinline__ ull f2fma(ull a, ull b, ull c) {
    ull d; asm("fma.rn.f32x2 %0,%1,%2,%3;" : "=l"(d) : "l"(a), "l"(b), "l"(c)); return d;
}
__device__ __forceinline__ ull f2add(ull a, ull b) {
    ull d; asm("add.rn.f32x2 %0,%1,%2;" : "=l"(d) : "l"(a), "l"(b)); return d;
}
__device__ __forceinline__ ull f2mul(ull a, ull b) {
    ull d; asm("mul.rn.f32x2 %0,%1,%2;" : "=l"(d) : "l"(a), "l"(b)); return d;
}

// ---------------- tf32 mma helpers ----------------
__device__ __forceinline__ unsigned f2tf(float x) {
    unsigned r; asm("cvt.rna.tf32.f32 %0,%1;" : "=r"(r) : "f"(x)); return r;
}
__device__ __forceinline__ void tfsplit(float x, unsigned& hi, unsigned& lo) {
    hi = f2tf(x);
    float res = x - __uint_as_float(hi);
    lo = f2tf(res);
}
__device__ __forceinline__ void mma_tf32(float c[4],
    unsigned a0, unsigned a1, unsigned a2, unsigned a3,
    unsigned b0, unsigned b1) {
    asm volatile(
        "mma.sync.aligned.m16n8k8.row.col.f32.tf32.tf32.f32 "
        "{%0,%1,%2,%3},{%4,%5,%6,%7},{%8,%9},{%0,%1,%2,%3};"
        : "+f"(c[0]), "+f"(c[1]), "+f"(c[2]), "+f"(c[3])
        : "r"(a0), "r"(a1), "r"(a2), "r"(a3), "r"(b0), "r"(b1));
}

// ---------------- device scratch ----------------
__device__ float  g_h0[BB*CC*PLANE];
__device__ float  g_h1[BB*CC*PLANE];
__device__ float2 g_G [BB*CC*HP*KY];
__device__ float2 g_F [BB*CC*MM*KY];
__device__ float2 g_T [BB*CC*HP*KY];
__device__ float2 g_WT[(size_t)NLAY*CC*CC*MM*KY];   // [l][i][o][mk] = {wr, wi}
__device__ uint2  g_EySp[HP*24];     // [y][2ky re/im] {hi,lo}
__device__ unsigned g_ICyh[KY*HP];
__device__ unsigned g_ICyl[KY*HP];
__device__ unsigned g_ISyh[KY*HP];
__device__ unsigned g_ISyl[KY*HP];
__device__ uint2  g_W1sp[128*32];
__device__ float2 g_Ex [MM*HP];
__device__ float2 g_Exi[MM*HP];
__device__ float  g_tmp[BB*2*SS*SS];

// Packed pair gelu: A&S 7.1.26 erf (4-term), f32x2, branchless.
__device__ __forceinline__ ull gelu2(ull x2) {
    ull z = f2mul(x2, dup2(0.70710678118654752440f));
    ull az; asm("and.b64 %0,%1,%2;" : "=l"(az) : "l"(z), "l"(0x7FFFFFFF7FFFFFFFULL));
    ull den = f2fma(az, dup2(0.3275911f), dup2(1.0f));
    float d0, d1; upk(d0, d1, den);
    ull tt = pk(__fdividef(1.0f, d0), __fdividef(1.0f, d1));
    ull p = f2fma(tt, dup2(1.061405429f), dup2(-1.453152027f));
    p = f2fma(p, tt, dup2(1.421413741f));
    p = f2fma(p, tt, dup2(-0.284496736f));
    p = f2fma(p, tt, dup2(0.254829592f));
    p = f2mul(p, tt);
    ull m  = f2mul(z, z);
    ull ea = f2mul(m, dup2(-1.4426950408889634f));
    float e0a, e1a; upk(e0a, e1a, ea);
    float e0, e1;
    asm("ex2.approx.f32 %0,%1;" : "=f"(e0) : "f"(e0a));
    asm("ex2.approx.f32 %0,%1;" : "=f"(e1) : "f"(e1a));
    ull e = pk(e0, e1);
    ull np; asm("xor.b64 %0,%1,%2;" : "=l"(np) : "l"(p), "l"(0x8000000080000000ULL));
    ull w = f2fma(np, e, dup2(1.0f));
    ull ws; asm("and.b64 %0,%1,%2;" : "=l"(ws) : "l"(w),  "l"(0x7FFFFFFF7FFFFFFFULL));
    ull xs; asm("and.b64 %0,%1,%2;" : "=l"(xs) : "l"(x2), "l"(0x8000000080000000ULL));
    ull wc; asm("or.b64 %0,%1,%2;"  : "=l"(wc) : "l"(ws), "l"(xs));
    ull s = f2fma(wc, dup2(0.5f), dup2(0.5f));
    return f2mul(x2, s);
}

// ---------------- basis tables ----------------
__global__ void k_basis() {
    int idx = blockIdx.x * blockDim.x + threadIdx.x;
    if (idx < KY*HP) {
        int ky = idx / HP, y = idx % HP;
        int r = (ky * y) % HP;
        float a = 6.28318530717958647692f * (float)r / (float)HP;
        float c = cosf(a), s = sinf(a);
        unsigned hh, ll;
        tfsplit(c, hh, ll);
        g_EySp[y*24 + 2*ky] = make_uint2(hh, ll);
        tfsplit(-s, hh, ll);
        g_EySp[y*24 + 2*ky + 1] = make_uint2(hh, ll);
        float al = (ky == 0) ? 1.0f : 2.0f;
        float inv = 1.0f / ((float)HP * (float)HP);
        tfsplit(al*inv*c, hh, ll);
        g_ICyh[idx] = hh; g_ICyl[idx] = ll;
        tfsplit(al*inv*s, hh, ll);
        g_ISyh[idx] = hh; g_ISyl[idx] = ll;
    }
    if (idx < MM*HP) {
        int m = idx / HP, xx = idx % HP;
        int kx = (m < KY) ? m : (264 + m);
        int r = (kx * xx) % HP;
        float a = 6.28318530717958647692f * (float)r / (float)HP;
        float c = cosf(a), s = sinf(a);
        g_Ex[idx]  = make_float2(c, -s);
        g_Exi[idx] = make_float2(c,  s);
    }
}

// ---------------- weight transpose + w1 split ----------------
__global__ void k_transw(const float* __restrict__ w1r, const float* __restrict__ w1i,
                         const float* __restrict__ w2r, const float* __restrict__ w2i,
                         const float* __restrict__ mw1) {
    int idx = blockIdx.x * blockDim.x + threadIdx.x;
    if (idx < 128*32) {
        unsigned hh, ll;
        tfsplit(mw1[idx], hh, ll);
        g_W1sp[idx] = make_uint2(hh, ll);
    }
    if (idx >= NLAY*MM*KY*CC*CC) return;
    int o  = idx & 31;
    int i  = (idx >> 5) & 31;
    int ky = (idx >> 10) % KY;
    int rest = idx / (1024 * KY);
    int m = rest % MM;
    int l = rest / MM;
    const float *sr, *si;
    int src;
    if (m < KY) {
        src = (((l*CC + i)*CC + o)*12 + m)*12 + ky;
        sr = w1r; si = w1i;
    } else {
        src = (((l*CC + i)*CC + o)*12 + (m - 12))*12 + ky;
        sr = w2r; si = w2i;
    }
    int mk = m*KY + ky;
    g_WT[(((size_t)(l*CC + i) * CC + o) * (MM*KY)) + mk] = make_float2(sr[src], si[src]);
}

#define HS2 296

// Shared MMA epilogue: G[32 x 24] = out[32 x 288] (in sH, stride HS2) x EySp.
// 8 warps: warp_m (2) x wk (4, K-split of 72). sRed: >= 1536 floats scratch.
__device__ __forceinline__ void dft_epilogue(const float* sH, float* sRed,
                                             int b, int x, int warp_m, int wk,
                                             int lr, int lc) {
    float acc2[3][4];
    #pragma unroll
    for (int nt = 0; nt < 3; nt++)
        #pragma unroll
        for (int j = 0; j < 4; j++) acc2[nt][j] = 0.0f;

    int row0 = warp_m*16 + lr;
    #pragma unroll
    for (int kb = 0; kb < 9; kb++) {
        int kk = wk*72 + kb*8 + lc;
        float a0f = sH[row0*HS2 + kk];
        float a1f = sH[(row0+8)*HS2 + kk];
        float a2f = sH[row0*HS2 + kk + 4];
        float a3f = sH[(row0+8)*HS2 + kk + 4];
        unsigned ah0, al0, ah1, al1, ah2, al2, ah3, al3;
        tfsplit(a0f, ah0, al0); tfsplit(a1f, ah1, al1);
        tfsplit(a2f, ah2, al2); tfsplit(a3f, ah3, al3);
        #pragma unroll
        for (int nt = 0; nt < 3; nt++) {
            uint2 b0 = __ldg(&g_EySp[kk*24 + nt*8 + lr]);
            uint2 b1 = __ldg(&g_EySp[(kk+4)*24 + nt*8 + lr]);
            mma_tf32(acc2[nt], ah0, ah1, ah2, ah3, b0.y, b1.y);
            mma_tf32(acc2[nt], al0, al1, al2, al3, b0.x, b1.x);
            mma_tf32(acc2[nt], ah0, ah1, ah2, ah3, b0.x, b1.x);
        }
    }

    // reduce 4 K-partials in 2 rounds
    if (wk >= 2) {
        float* dst = sRed + ((wk-2)*2 + warp_m)*384;
        #pragma unroll
        for (int nt = 0; nt < 3; nt++)
            #pragma unroll
            for (int j = 0; j < 4; j++)
                dst[(lr + (j>>1)*8)*24 + nt*8 + 2*lc + (j&1)] = acc2[nt][j];
    }
    __syncthreads();
    if (wk < 2) {
        const float* src = sRed + (wk*2 + warp_m)*384;
        #pragma unroll
        for (int nt = 0; nt < 3; nt++)
            #pragma unroll
            for (int j = 0; j < 4; j++)
                acc2[nt][j] += src[(lr + (j>>1)*8)*24 + nt*8 + 2*lc + (j&1)];
    }
    __syncthreads();
    if (wk == 1) {
        float* dst = sRed + warp_m*384;
        #pragma unroll
        for (int nt = 0; nt < 3; nt++)
            #pragma unroll
            for (int j = 0; j < 4; j++)
                dst[(lr + (j>>1)*8)*24 + nt*8 + 2*lc + (j&1)] = acc2[nt][j];
    }
    __syncthreads();
    if (wk == 0) {
        const float* src = sRed + warp_m*384;
        #pragma unroll
        for (int nt = 0; nt < 3; nt++)
            #pragma unroll
            for (int j = 0; j < 4; j++)
                acc2[nt][j] += src[(lr + (j>>1)*8)*24 + nt*8 + 2*lc + (j&1)];
        float* gg0 = (float*)g_G + (((size_t)(b*CC + row0)*HP + x)*24);
        float* gg1 = (float*)g_G + (((size_t)(b*CC + row0 + 8)*HP + x)*24);
        #pragma unroll
        for (int nt = 0; nt < 3; nt++) {
            *(float2*)(gg0 + nt*8 + 2*lc) = make_float2(acc2[nt][0], acc2[nt][1]);
            *(float2*)(gg1 + nt*8 + 2*lc) = make_float2(acc2[nt][2], acc2[nt][3]);
        }
    }
}

// ---------------- stage 0: embed + fused y-DFT ----------------
// grid B*HP (block = (b,x)), 256 threads.
__global__ void __launch_bounds__(256) k_embed(const float* __restrict__ xin,
                                               const int* __restrict__ d2v,
                                               const float* __restrict__ fw,
                                               const float* __restrict__ fb,
                                               float* __restrict__ hout) {
    __shared__ __align__(16) float sH[32*HS2];
    __shared__ __align__(16) float sRed[1536];
    __shared__ float sV[SS];
    __shared__ float sFw[96];
    __shared__ float sFb[CC];
    int blk = blockIdx.x;
    int b = blk / HP, x = blk % HP;
    int t = threadIdx.x;
    bool xv = (x < SS);

    if (t < 96) sFw[t] = fw[t];
    if (t < CC) sFb[t] = fb[t];
    if (xv && t < SS) sV[t] = xin[b*SS*SS + d2v[x*SS + t]];
    __syncthreads();

    if (!xv) {
        // pad rows: zero h and zero G
        for (int idx = t; idx < 32*HP; idx += 256) {
            int c = idx / HP, y = idx % HP;
            hout[(size_t)(b*CC + c)*PLANE + (size_t)x*HP + y] = 0.0f;
        }
        for (int idx = t; idx < 32*24; idx += 256) {
            int c = idx / 24;
            ((float*)g_G)[((size_t)(b*CC + c)*HP + x)*24 + (idx % 24)] = 0.0f;
        }
        return;
    }

    const float inv255 = 1.0f / 255.0f;
    float gi = (float)x * inv255;
    for (int idx = t; idx < 32*HP; idx += 256) {
        int c = idx / HP, y = idx % HP;
        float val = 0.0f;
        if (y < SS)
            val = sFw[3*c]*sV[y] + sFw[3*c+1]*gi + sFw[3*c+2]*((float)y*inv255) + sFb[c];
        hout[(size_t)(b*CC + c)*PLANE + (size_t)x*HP + y] = val;
        sH[c*HS2 + y] = val;
    }
    __syncthreads();

    int wid = t >> 5, lane = t & 31;
    dft_epilogue(sH, sRed, b, x, wid & 1, wid >> 1, lane >> 2, lane & 3);
}

// ---------------- B: x-DFT onto 24 modes ----------------
__global__ void __launch_bounds__(288) k_xdft() {
    __shared__ float2 sG[HP*KY];
    int bc = blockIdx.x, t = threadIdx.x;
    const float2* Gp = g_G + (size_t)bc * HP * KY;
    for (int i = t; i < HP*KY; i += 288) sG[i] = Gp[i];
    __syncthreads();
    int m = t / KY, ky = t % KY;
    float accx = 0.0f, accy = 0.0f;
    const float2* ex = g_Ex + m * HP;
    for (int x = 0; x < HP; x++) {
        float2 g = sG[x*KY + ky];
        float2 e = ex[x];
        accx += g.x*e.x - g.y*e.y;
        accy += g.x*e.y + g.y*e.x;
    }
    g_F[((size_t)bc * MM + m) * KY + ky] = make_float2(accx, accy);
}

// ---------------- C+D fused: channel mix + inverse x-DFT ----------------
__global__ void __launch_bounds__(288) k_mixix(int l) {
    __shared__ float2 sO[MM*KY];
    int bo = blockIdx.x;
    int b = bo >> 5, o = bo & 31;
    int t = threadIdx.x;

    {
        const float2* wp = g_WT + ((size_t)(l*CC) * CC + o) * (MM*KY) + t;
        const float2* Fp = g_F + (size_t)b * CC * (MM*KY) + t;
        float accr = 0.0f, acci = 0.0f;
        #pragma unroll 8
        for (int i = 0; i < CC; i++) {
            float2 w = wp[(size_t)i * CC * (MM*KY)];
            float2 f = Fp[(size_t)i * (MM*KY)];
            accr += f.x*w.x - f.y*w.y;
            acci += f.x*w.y + f.y*w.x;
        }
        sO[t] = make_float2(accr, acci);
    }
    __syncthreads();

    float2 acc[KY];
    #pragma unroll
    for (int q = 0; q < KY; q++) acc[q] = make_float2(0.0f, 0.0f);
    #pragma unroll 4
    for (int m = 0; m < MM; m++) {
        float2 e = g_Exi[m*HP + t];
        #pragma unroll
        for (int q = 0; q < KY; q++) {
            float2 ov = sO[m*KY + q];
            acc[q].x += ov.x*e.x - ov.y*e.y;
            acc[q].y += ov.x*e.y + ov.y*e.x;
        }
    }
    float2* out = g_T + ((size_t)bo * HP + t) * KY;
    #pragma unroll
    for (int q = 0; q < KY; q++) out[q] = acc[q];
}

// ---------------- E: fused conv + inverse y-DFT + (fused forward y-DFT) ----------------
#define WS 68
__global__ void __launch_bounds__(256) k_layer(const float* __restrict__ hin,
                                               float* __restrict__ hout,
                                               const float* __restrict__ conv_w,
                                               const float* __restrict__ conv_b,
                                               int l, int fuse) {
    __shared__ __align__(16) float sH[32*HS2];
    __shared__ __align__(16) float sW[32*WS];   // >= 1536 floats; reused as sRed
    __shared__ float scb[CC];
    int blk = blockIdx.x;
    int b = blk / HP, x = blk % HP;
    int t = threadIdx.x;

    for (int idx = t; idx < 32*72; idx += 256) {
        int r = idx / 72, c4 = (idx % 72) * 4;
        float4 v = *(const float4*)(hin + (size_t)(b*CC + r)*PLANE + (size_t)x*HP + c4);
        *(float4*)(sH + r*HS2 + c4) = v;
    }
    for (int idx = t; idx < 32*56; idx += 256) {
        int o = idx / 56, c = idx % 56;
        float w;
        if (c < 32)
            w = conv_w[l*CC*CC + o*CC + c];
        else if (c < 44)
            w = g_T[((size_t)(b*CC + o)*HP + x)*KY + (c-32)].x;
        else
            w = -g_T[((size_t)(b*CC + o)*HP + x)*KY + (c-44)].y;
        sW[o*WS + c] = w;
    }
    if (t < CC) scb[t] = conv_b[l*CC + t];
    __syncthreads();

    int wid = t >> 5, lane = t & 31;
    int warp_m = wid & 1, warp_n = wid >> 1;
    int lr = lane >> 2, lc = lane & 3;

    float acc[9][4];
    #pragma unroll
    for (int nt = 0; nt < 9; nt++)
        #pragma unroll
        for (int j = 0; j < 4; j++) acc[nt][j] = 0.0f;

    int row0 = warp_m*16 + lr;

    #pragma unroll
    for (int kb = 0; kb < 4; kb++) {
        int kk = kb*8 + lc;
        float a0f = sW[row0*WS + kk];
        float a1f = sW[(row0+8)*WS + kk];
        float a2f = sW[row0*WS + kk + 4];
        float a3f = sW[(row0+8)*WS + kk + 4];
        unsigned ah0, al0, ah1, al1, ah2, al2, ah3, al3;
        tfsplit(a0f, ah0, al0); tfsplit(a1f, ah1, al1);
        tfsplit(a2f, ah2, al2); tfsplit(a3f, ah3, al3);
        #pragma unroll
        for (int nt = 0; nt < 9; nt++) {
            int nb = warp_n*72 + nt*8 + lr;
            float b0f = sH[kk*HS2 + nb];
            float b1f = sH[(kk+4)*HS2 + nb];
            unsigned bh0, bl0, bh1, bl1;
            tfsplit(b0f, bh0, bl0);
            tfsplit(b1f, bh1, bl1);
            mma_tf32(acc[nt], ah0, ah1, ah2, ah3, bl0, bl1);
            mma_tf32(acc[nt], al0, al1, al2, al3, bh0, bh1);
            mma_tf32(acc[nt], ah0, ah1, ah2, ah3, bh0, bh1);
        }
    }
    #pragma unroll
    for (int kb = 4; kb < 7; kb++) {
        int kk = kb*8 + lc;
        float a0f = sW[row0*WS + kk];
        float a1f = sW[(row0+8)*WS + kk];
        float a2f = sW[row0*WS + kk + 4];
        float a3f = sW[(row0+8)*WS + kk + 4];
        unsigned ah0, al0, ah1, al1, ah2, al2, ah3, al3;
        tfsplit(a0f, ah0, al0); tfsplit(a1f, ah1, al1);
        tfsplit(a2f, ah2, al2); tfsplit(a3f, ah3, al3);
        int q0 = kk - 32, q1 = kk - 28;
        const unsigned* t0h = (q0 < 12) ? (g_ICyh + q0*HP) : (g_ISyh + (q0-12)*HP);
        const unsigned* t0l = (q0 < 12) ? (g_ICyl + q0*HP) : (g_ISyl + (q0-12)*HP);
        const unsigned* t1h = (q1 < 12) ? (g_ICyh + q1*HP) : (g_ISyh + (q1-12)*HP);
        const unsigned* t1l = (q1 < 12) ? (g_ICyl + q1*HP) : (g_ISyl + (q1-12)*HP);
        #pragma unroll
        for (int nt = 0; nt < 9; nt++) {
            int y = warp_n*72 + nt*8 + lr;
            unsigned bh0 = __ldg(&t0h[y]);
            unsigned bl0 = __ldg(&t0l[y]);
            unsigned bh1 = __ldg(&t1h[y]);
            unsigned bl1 = __ldg(&t1l[y]);
            mma_tf32(acc[nt], ah0, ah1, ah2, ah3, bl0, bl1);
            mma_tf32(acc[nt], al0, al1, al2, al3, bh0, bh1);
            mma_tf32(acc[nt], ah0, ah1, ah2, ah3, bh0, bh1);
        }
    }

    if (fuse) __syncthreads();   // all sH/sW reads done before overwrite

    int o0 = warp_m*16 + lr;
    ull b0p = dup2(scb[o0]), b1p = dup2(scb[o0 + 8]);
    float* base0 = hout + (size_t)(b*CC + o0)*PLANE + (size_t)x*HP;
    float* base1 = hout + (size_t)(b*CC + o0 + 8)*PLANE + (size_t)x*HP;
    #pragma unroll
    for (int nt = 0; nt < 9; nt++) {
        int y = warp_n*72 + nt*8 + 2*lc;
        ull a01 = f2add(pk(acc[nt][0], acc[nt][1]), b0p);
        ull a23 = f2add(pk(acc[nt][2], acc[nt][3]), b1p);
        if (fuse) {
            a01 = gelu2(a01); a23 = gelu2(a23);
            *(ull*)(sH + o0*HS2 + y)       = a01;
            *(ull*)(sH + (o0 + 8)*HS2 + y) = a23;
        }
        *(ull*)(base0 + y) = a01;
        *(ull*)(base1 + y) = a23;
    }

    if (!fuse) return;
    __syncthreads();
    dft_epilogue(sH, sW, b, x, warp_m, warp_n, lr, lc);
}

// ---------------- final MLP 32 -> 128 (gelu) -> 2 as tf32 MMA ----------------
#define SBS 136
__global__ void __launch_bounds__(256) k_mlp(const float* __restrict__ hin,
                                             const float* __restrict__ b1,
                                             const float* __restrict__ w2,
                                             const float* __restrict__ b2) {
    __shared__ __align__(16) float sB[32*SBS];
    __shared__ float sw2[256];
    __shared__ float sb1[128];
    __shared__ float sD[512];
    int t = threadIdx.x;
    int blk = blockIdx.x;
    int b = blk >> 8, ii = blk & 255;
    int yh = blockIdx.y;

    #pragma unroll
    for (int k = 0; k < 4; k++) {
        int idx = t + k*256;
        int row = idx >> 5, c4 = (idx & 31) * 4;
        float4 v = *(const float4*)(hin + (size_t)(b*CC + row)*PLANE + (size_t)ii*HP + yh*128 + c4);
        *(float4*)(sB + row*SBS + c4) = v;
    }
    if (t < 128) sb1[t] = b1[t];
    sw2[t] = w2[t];
    __syncthreads();

    int wid = t >> 5, lane = t & 31;
    int lr = lane >> 2, lc = lane & 3;
    int yg = wid & 3, hh = wid >> 2;
    int ybl = yg * 32;

    ull d2[8];
    #pragma unroll
    for (int i = 0; i < 8; i++) d2[i] = 0ull;

    #pragma unroll
    for (int mtp = 0; mtp < 2; mtp++) {
        int h0 = hh*64 + mtp*32;
        float acc[2][4][4];
        #pragma unroll
        for (int m2 = 0; m2 < 2; m2++) {
            float ba = sb1[h0 + m2*16 + lr];
            float bb = sb1[h0 + m2*16 + lr + 8];
            #pragma unroll
            for (int nt = 0; nt < 4; nt++) {
                acc[m2][nt][0] = ba; acc[m2][nt][1] = ba;
                acc[m2][nt][2] = bb; acc[m2][nt][3] = bb;
            }
        }
        #pragma unroll
        for (int kb = 0; kb < 4; kb++) {
            int kk = kb*8 + lc;
            unsigned bh[4][2], bl[4][2];
            #pragma unroll
            for (int nt = 0; nt < 4; nt++) {
                float b0f = sB[kk*SBS + ybl + nt*8 + lr];
                float b1f = sB[(kk+4)*SBS + ybl + nt*8 + lr];
                tfsplit(b0f, bh[nt][0], bl[nt][0]);
                tfsplit(b1f, bh[nt][1], bl[nt][1]);
            }
            #pragma unroll
            for (int m2 = 0; m2 < 2; m2++) {
                int hb = h0 + m2*16;
                uint2 a0 = __ldg(&g_W1sp[(hb+lr)*32 + kk]);
                uint2 a1 = __ldg(&g_W1sp[(hb+lr+8)*32 + kk]);
                uint2 a2 = __ldg(&g_W1sp[(hb+lr)*32 + kk + 4]);
                uint2 a3 = __ldg(&g_W1sp[(hb+lr+8)*32 + kk + 4]);
                #pragma unroll
                for (int nt = 0; nt < 4; nt++) {
                    mma_tf32(acc[m2][nt], a0.x, a1.x, a2.x, a3.x, bl[nt][0], bl[nt][1]);
                    mma_tf32(acc[m2][nt], a0.y, a1.y, a2.y, a3.y, bh[nt][0], bh[nt][1]);
                    mma_tf32(acc[m2][nt], a0.x, a1.x, a2.x, a3.x, bh[nt][0], bh[nt][1]);
                }
            }
        }
        #pragma unroll
        for (int m2 = 0; m2 < 2; m2++) {
            int ha = h0 + m2*16 + lr, hb2 = ha + 8;
            ull w2a0 = dup2(sw2[ha]),  w2a1 = dup2(sw2[128 + ha]);
            ull w2b0 = dup2(sw2[hb2]), w2b1 = dup2(sw2[128 + hb2]);
            #pragma unroll
            for (int nt = 0; nt < 4; nt++) {
                ull g01 = gelu2(pk(acc[m2][nt][0], acc[m2][nt][1]));
                ull g23 = gelu2(pk(acc[m2][nt][2], acc[m2][nt][3]));
                d2[nt]     = f2fma(w2a0, g01, d2[nt]);
                d2[nt]     = f2fma(w2b0, g23, d2[nt]);
                d2[4 + nt] = f2fma(w2a1, g01, d2[4 + nt]);
                d2[4 + nt] = f2fma(w2b1, g23, d2[4 + nt]);
            }
        }
    }

    float d[16];
    #pragma unroll
    for (int nt = 0; nt < 4; nt++) {
        upk(d[nt*2], d[nt*2+1], d2[nt]);
        upk(d[8 + nt*2], d[8 + nt*2 + 1], d2[4 + nt]);
    }

    #pragma unroll
    for (int i = 0; i < 16; i++) {
        d[i] += __shfl_xor_sync(0xffffffffu, d[i], 4);
        d[i] += __shfl_xor_sync(0xffffffffu, d[i], 8);
        d[i] += __shfl_xor_sync(0xffffffffu, d[i], 16);
    }
    if (lr == 0) {
        #pragma unroll
        for (int i = 0; i < 16; i++) sD[wid*64 + lc*16 + i] = d[i];
    }
    __syncthreads();
    {
        int j = t & 1, yl = t >> 1;
        int yg2 = yl >> 5, cc2 = yl & 31;
        int nt = cc2 >> 3, rem = cc2 & 7, lc2 = rem >> 1, c01 = rem & 1;
        int k = j*8 + nt*2 + c01;
        float val = sD[yg2*64 + lc2*16 + k] + sD[(4+yg2)*64 + lc2*16 + k] + __ldg(&b2[j]);
        int p = ii*SS + yh*128 + yl;
        g_tmp[(size_t)(b*2 + j)*(SS*SS) + p] = val;
    }
}

// ---------------- output permutation ----------------
__global__ void k_scatter(const int* __restrict__ v2d, float* __restrict__ out) {
    int idx = blockIdx.x * blockDim.x + threadIdx.x;
    if (idx >= BB*SS*SS) return;
    int b = idx >> 16, n = idx & 65535;
    int p = v2d[n];
    float v0 = g_tmp[(size_t)(b*2    ) * SS*SS + p];
    float v1 = g_tmp[(size_t)(b*2 + 1) * SS*SS + p];
    reinterpret_cast<float2*>(out)[idx] = make_float2(v0, v1);
}

// ---------------- launch ----------------
extern "C" void kernel_launch(void* const* d_in, const int* in_sizes, int n_in,
                              void* d_out, int out_size) {
    const float* x    = (const float*)d_in[0];
    const int*   d2v  = (const int*)  d_in[1];
    const int*   v2d  = (const int*)  d_in[2];
    const float* fc0w = (const float*)d_in[3];
    const float* fc0b = (const float*)d_in[4];
    const float* w1r  = (const float*)d_in[5];
    const float* w1i  = (const float*)d_in[6];
    const float* w2r  = (const float*)d_in[7];
    const float* w2i  = (const float*)d_in[8];
    const float* cw   = (const float*)d_in[9];
    const float* cb   = (const float*)d_in[10];
    const float* mw1  = (const float*)d_in[11];
    const float* mb1  = (const float*)d_in[12];
    const float* mw2  = (const float*)d_in[13];
    const float* mb2  = (const float*)d_in[14];

    float *h0, *h1;
    cudaGetSymbolAddress((void**)&h0, g_h0);
    cudaGetSymbolAddress((void**)&h1, g_h1);

    k_basis<<<(MM*HP + 255)/256, 256>>>();
    k_transw<<<(NLAY*MM*KY*CC*CC + 255)/256, 256>>>(w1r, w1i, w2r, w2i, mw1);
    k_embed<<<BB*HP, 256>>>(x, d2v, fc0w, fc0b, h0);

    float* cur = h0;
    float* nxt = h1;
    for (int l = 0; l < NLAY; l++) {
        k_xdft<<<BB*CC, 288>>>();
        k_mixix<<<BB*CC, 288>>>(l);
        k_layer<<<BB*HP, 256>>>(cur, nxt, cw, cb, l, (l < NLAY-1) ? 1 : 0);
        float* tp = cur; cur = nxt; nxt = tp;
    }
    k_mlp<<<dim3(BB*SS, 2), 256>>>(cur, mb1, mw2, mb2);
    k_scatter<<<(BB*SS*SS + 255)/256, 256>>>(v2d, (float*)d_out);
}

// round 16
// speedup vs baseline: 1.0532x; 1.0532x over previous
#include <cuda_runtime.h>
#include <math.h>

#define BB 8
#define CC 32
#define SS 256
#define HP 288
#define KY 12
#define MM 24
#define NLAY 4
#define PLANE (HP*HP)

typedef unsigned long long ull;

// ---------------- packed f32x2 helpers ----------------
__device__ __forceinline__ ull pk(float lo, float hi) {
    ull r; asm("mov.b64 %0,{%1,%2};" : "=l"(r) : "f"(lo), "f"(hi)); return r;
}
__device__ __forceinline__ ull dup2(float v) { return pk(v, v); }
__device__ __forceinline__ void upk(float& lo, float& hi, ull v) {
    asm("mov.b64 {%0,%1},%2;" : "=f"(lo), "=f"(hi) : "l"(v));
}
__device__ __forceinline__ ull f2fma(ull a, ull b, ull c) {
    ull d; asm("fma.rn.f32x2 %0,%1,%2,%3;" : "=l"(d) : "l"(a), "l"(b), "l"(c)); return d;
}
__device__ __forceinline__ ull f2add(ull a, ull b) {
    ull d; asm("add.rn.f32x2 %0,%1,%2;" : "=l"(d) : "l"(a), "l"(b)); return d;
}
__device__ __forceinline__ ull f2mul(ull a, ull b) {
    ull d; asm("mul.rn.f32x2 %0,%1,%2;" : "=l"(d) : "l"(a), "l"(b)); return d;
}

// ---------------- tf32 mma helpers ----------------
__device__ __forceinline__ unsigned f2tf(float x) {
    unsigned r; asm("cvt.rna.tf32.f32 %0,%1;" : "=r"(r) : "f"(x)); return r;
}
__device__ __forceinline__ void tfsplit(float x, unsigned& hi, unsigned& lo) {
    hi = f2tf(x);
    float res = x - __uint_as_float(hi);
    lo = f2tf(res);
}
__device__ __forceinline__ void mma_tf32(float c[4],
    unsigned a0, unsigned a1, unsigned a2, unsigned a3,
    unsigned b0, unsigned b1) {
    asm volatile(
        "mma.sync.aligned.m16n8k8.row.col.f32.tf32.tf32.f32 "
        "{%0,%1,%2,%3},{%4,%5,%6,%7},{%8,%9},{%0,%1,%2,%3};"
        : "+f"(c[0]), "+f"(c[1]), "+f"(c[2]), "+f"(c[3])
        : "r"(a0), "r"(a1), "r"(a2), "r"(a3), "r"(b0), "r"(b1));
}

// ---------------- cp.async ----------------
__device__ __forceinline__ void cpasync16(void* smem, const void* g) {
    unsigned s = (unsigned)__cvta_generic_to_shared(smem);
    asm volatile("cp.async.ca.shared.global [%0], [%1], 16;" :: "r"(s), "l"(g));
}

// ---------------- device scratch ----------------
__device__ float  g_h0[BB*CC*PLANE];
__device__ float  g_h1[BB*CC*PLANE];
__device__ float2 g_G [BB*CC*HP*KY];
__device__ float2 g_F [BB*CC*MM*KY];
__device__ float2 g_T [BB*CC*HP*KY];
__device__ float2 g_WT[(size_t)NLAY*CC*CC*MM*KY];   // [l][i][o][mk] = {wr, wi}
__device__ uint2  g_EySp[HP*24];     // [y][2ky re/im] {hi,lo}
__device__ unsigned g_ICyh[KY*HP];
__device__ unsigned g_ICyl[KY*HP];
__device__ unsigned g_ISyh[KY*HP];
__device__ unsigned g_ISyl[KY*HP];
__device__ uint2  g_W1sp[128*32];
__device__ float2 g_Ex [MM*HP];
__device__ float2 g_Exi[MM*HP];
__device__ float  g_tmp[BB*2*SS*SS];

// Packed pair gelu: A&S 7.1.26 erf (4-term), f32x2, branchless.
__device__ __forceinline__ ull gelu2(ull x2) {
    ull z = f2mul(x2, dup2(0.70710678118654752440f));
    ull az; asm("and.b64 %0,%1,%2;" : "=l"(az) : "l"(z), "l"(0x7FFFFFFF7FFFFFFFULL));
    ull den = f2fma(az, dup2(0.3275911f), dup2(1.0f));
    float d0, d1; upk(d0, d1, den);
    ull tt = pk(__fdividef(1.0f, d0), __fdividef(1.0f, d1));
    ull p = f2fma(tt, dup2(1.061405429f), dup2(-1.453152027f));
    p = f2fma(p, tt, dup2(1.421413741f));
    p = f2fma(p, tt, dup2(-0.284496736f));
    p = f2fma(p, tt, dup2(0.254829592f));
    p = f2mul(p, tt);
    ull m  = f2mul(z, z);
    ull ea = f2mul(m, dup2(-1.4426950408889634f));
    float e0a, e1a; upk(e0a, e1a, ea);
    float e0, e1;
    asm("ex2.approx.f32 %0,%1;" : "=f"(e0) : "f"(e0a));
    asm("ex2.approx.f32 %0,%1;" : "=f"(e1) : "f"(e1a));
    ull e = pk(e0, e1);
    ull np; asm("xor.b64 %0,%1,%2;" : "=l"(np) : "l"(p), "l"(0x8000000080000000ULL));
    ull w = f2fma(np, e, dup2(1.0f));
    ull ws; asm("and.b64 %0,%1,%2;" : "=l"(ws) : "l"(w),  "l"(0x7FFFFFFF7FFFFFFFULL));
    ull xs; asm("and.b64 %0,%1,%2;" : "=l"(xs) : "l"(x2), "l"(0x8000000080000000ULL));
    ull wc; asm("or.b64 %0,%1,%2;"  : "=l"(wc) : "l"(ws), "l"(xs));
    ull s = f2fma(wc, dup2(0.5f), dup2(0.5f));
    return f2mul(x2, s);
}

// ---------------- basis tables ----------------
__global__ void k_basis() {
    int idx = blockIdx.x * blockDim.x + threadIdx.x;
    if (idx < KY*HP) {
        int ky = idx / HP, y = idx % HP;
        int r = (ky * y) % HP;
        float a = 6.28318530717958647692f * (float)r / (float)HP;
        float c = cosf(a), s = sinf(a);
        unsigned hh, ll;
        tfsplit(c, hh, ll);
        g_EySp[y*24 + 2*ky] = make_uint2(hh, ll);
        tfsplit(-s, hh, ll);
        g_EySp[y*24 + 2*ky + 1] = make_uint2(hh, ll);
        float al = (ky == 0) ? 1.0f : 2.0f;
        float inv = 1.0f / ((float)HP * (float)HP);
        tfsplit(al*inv*c, hh, ll);
        g_ICyh[idx] = hh; g_ICyl[idx] = ll;
        tfsplit(al*inv*s, hh, ll);
        g_ISyh[idx] = hh; g_ISyl[idx] = ll;
    }
    if (idx < MM*HP) {
        int m = idx / HP, xx = idx % HP;
        int kx = (m < KY) ? m : (264 + m);
        int r = (kx * xx) % HP;
        float a = 6.28318530717958647692f * (float)r / (float)HP;
        float c = cosf(a), s = sinf(a);
        g_Ex[idx]  = make_float2(c, -s);
        g_Exi[idx] = make_float2(c,  s);
    }
}

// ---------------- weight transpose + w1 split ----------------
__global__ void k_transw(const float* __restrict__ w1r, const float* __restrict__ w1i,
                         const float* __restrict__ w2r, const float* __restrict__ w2i,
                         const float* __restrict__ mw1) {
    int idx = blockIdx.x * blockDim.x + threadIdx.x;
    if (idx < 128*32) {
        unsigned hh, ll;
        tfsplit(mw1[idx], hh, ll);
        g_W1sp[idx] = make_uint2(hh, ll);
    }
    if (idx >= NLAY*MM*KY*CC*CC) return;
    int o  = idx & 31;
    int i  = (idx >> 5) & 31;
    int ky = (idx >> 10) % KY;
    int rest = idx / (1024 * KY);
    int m = rest % MM;
    int l = rest / MM;
    const float *sr, *si;
    int src;
    if (m < KY) {
        src = (((l*CC + i)*CC + o)*12 + m)*12 + ky;
        sr = w1r; si = w1i;
    } else {
        src = (((l*CC + i)*CC + o)*12 + (m - 12))*12 + ky;
        sr = w2r; si = w2i;
    }
    int mk = m*KY + ky;
    g_WT[(((size_t)(l*CC + i) * CC + o) * (MM*KY)) + mk] = make_float2(sr[src], si[src]);
}

// ---------------- stage 0: embed ----------------
__global__ void k_embed(const float* __restrict__ xin, const int* __restrict__ d2v,
                        const float* __restrict__ fw, const float* __restrict__ fb,
                        float* __restrict__ hout) {
    int idx = blockIdx.x * blockDim.x + threadIdx.x;
    if (idx >= BB*PLANE) return;
    int b = idx / PLANE;
    int rem = idx % PLANE;
    int i = rem / HP, j = rem % HP;
    float* hp = hout + (size_t)b * CC * PLANE + rem;
    if (i < SS && j < SS) {
        float v  = xin[b*SS*SS + d2v[i*SS + j]];
        float gi = (float)i * (1.0f/255.0f);
        float gj = (float)j * (1.0f/255.0f);
        #pragma unroll
        for (int c = 0; c < CC; c++)
            hp[(size_t)c*PLANE] = fw[c*3]*v + fw[c*3+1]*gi + fw[c*3+2]*gj + fb[c];
    } else {
        #pragma unroll
        for (int c = 0; c < CC; c++) hp[(size_t)c*PLANE] = 0.0f;
    }
}

// ---------------- A: truncated y-DFT, tf32 MMA, smem-staged split twiddles ----------------
// grid (B*C, 3), block 192 = 6 warps x 16 rows. K in 9 chunks of 32, double-buffered.
#define AS 36
__global__ void __launch_bounds__(192) k_ydft(const float* __restrict__ h) {
    __shared__ __align__(16) float sA[2][96*AS];
    __shared__ __align__(16) uint2 sE[2][32*24];
    int t = threadIdx.x;
    int bc = blockIdx.x;
    const float* A = h + (size_t)bc * PLANE + (size_t)(blockIdx.y * 96) * HP;

    #pragma unroll
    for (int k = 0; k < 4; k++) {
        int idx = t + k*192;
        int row = idx >> 3, c4 = (idx & 7) * 4;
        cpasync16(&sA[0][row*AS + c4], A + (size_t)row*HP + c4);
    }
    #pragma unroll
    for (int k = 0; k < 2; k++) {
        int idx = t + k*192;
        cpasync16(&sE[0][idx*2], g_EySp + idx*2);
    }
    asm volatile("cp.async.commit_group;");

    int wid = t >> 5, lane = t & 31;
    int lr = lane >> 2, lc = lane & 3;

    float acc[3][4];
    #pragma unroll
    for (int nt = 0; nt < 3; nt++)
        #pragma unroll
        for (int j = 0; j < 4; j++) acc[nt][j] = 0.0f;

    for (int c = 0; c < 9; c++) {
        if (c + 1 < 9) {
            const float* src = A + (c+1)*32;
            #pragma unroll
            for (int k = 0; k < 4; k++) {
                int idx = t + k*192;
                int row = idx >> 3, c4 = (idx & 7) * 4;
                cpasync16(&sA[(c+1)&1][row*AS + c4], src + (size_t)row*HP + c4);
            }
            const uint2* esrc = g_EySp + (c+1)*32*24;
            #pragma unroll
            for (int k = 0; k < 2; k++) {
                int idx = t + k*192;
                cpasync16(&sE[(c+1)&1][idx*2], esrc + idx*2);
            }
            asm volatile("cp.async.commit_group;");
            asm volatile("cp.async.wait_group 1;");
        } else {
            asm volatile("cp.async.wait_group 0;");
        }
        __syncthreads();

        const float* a = sA[c&1] + wid*16*AS;
        const uint2* e = sE[c&1];
        #pragma unroll
        for (int kb = 0; kb < 4; kb++) {
            int kk = kb*8 + lc;
            float a0f = a[lr*AS + kk];
            float a1f = a[(lr+8)*AS + kk];
            float a2f = a[lr*AS + kk + 4];
            float a3f = a[(lr+8)*AS + kk + 4];
            unsigned ah0, al0, ah1, al1, ah2, al2, ah3, al3;
            tfsplit(a0f, ah0, al0); tfsplit(a1f, ah1, al1);
            tfsplit(a2f, ah2, al2); tfsplit(a3f, ah3, al3);
            #pragma unroll
            for (int nt = 0; nt < 3; nt++) {
                uint2 b0 = e[kk*24 + nt*8 + lr];
                uint2 b1 = e[(kk+4)*24 + nt*8 + lr];
                mma_tf32(acc[nt], ah0, ah1, ah2, ah3, b0.y, b1.y);
                mma_tf32(acc[nt], al0, al1, al2, al3, b0.x, b1.x);
                mma_tf32(acc[nt], ah0, ah1, ah2, ah3, b0.x, b1.x);
            }
        }
        __syncthreads();
    }

    int x0 = blockIdx.y * 96 + wid * 16;
    float2* out0 = g_G + ((size_t)bc * HP + x0 + lr) * KY;
    float2* out1 = out0 + 8 * KY;
    #pragma unroll
    for (int nt = 0; nt < 3; nt++) {
        out0[nt*4 + lc] = make_float2(acc[nt][0], acc[nt][1]);
        out1[nt*4 + lc] = make_float2(acc[nt][2], acc[nt][3]);
    }
}

// ---------------- B: x-DFT onto 24 modes; 2-way x-split for latency ----------------
// grid B*C, block 576 = 2 halves x 288 (m,ky) threads.
__global__ void __launch_bounds__(576) k_xdft() {
    __shared__ float2 sG[HP*KY];
    __shared__ float2 sP[288];
    int bc = blockIdx.x, t = threadIdx.x;
    const float2* Gp = g_G + (size_t)bc * HP * KY;
    for (int i = t; i < HP*KY; i += 576) sG[i] = Gp[i];
    __syncthreads();
    int half = t / 288, mk = t % 288;
    int m = mk / KY, ky = mk % KY;
    float accx = 0.0f, accy = 0.0f;
    const float2* ex = g_Ex + m * HP + half * 144;
    const float2* gp = sG + (size_t)(half * 144) * KY + ky;
    #pragma unroll 4
    for (int x = 0; x < 144; x++) {
        float2 g = gp[x*KY];
        float2 e = ex[x];
        accx += g.x*e.x - g.y*e.y;
        accy += g.x*e.y + g.y*e.x;
    }
    if (half == 1) sP[mk] = make_float2(accx, accy);
    __syncthreads();
    if (half == 0) {
        float2 p = sP[mk];
        g_F[(size_t)bc * MM * KY + mk] = make_float2(accx + p.x, accy + p.y);
    }
}

// ---------------- C+D fused: channel mix + inverse x-DFT ----------------
__global__ void __launch_bounds__(288) k_mixix(int l) {
    __shared__ float2 sO[MM*KY];
    int bo = blockIdx.x;
    int b = bo >> 5, o = bo & 31;
    int t = threadIdx.x;

    {
        const float2* wp = g_WT + ((size_t)(l*CC) * CC + o) * (MM*KY) + t;
        const float2* Fp = g_F + (size_t)b * CC * (MM*KY) + t;
        float accr = 0.0f, acci = 0.0f;
        #pragma unroll 8
        for (int i = 0; i < CC; i++) {
            float2 w = wp[(size_t)i * CC * (MM*KY)];
            float2 f = Fp[(size_t)i * (MM*KY)];
            accr += f.x*w.x - f.y*w.y;
            acci += f.x*w.y + f.y*w.x;
        }
        sO[t] = make_float2(accr, acci);
    }
    __syncthreads();

    float2 acc[KY];
    #pragma unroll
    for (int q = 0; q < KY; q++) acc[q] = make_float2(0.0f, 0.0f);
    #pragma unroll 4
    for (int m = 0; m < MM; m++) {
        float2 e = g_Exi[m*HP + t];
        #pragma unroll
        for (int q = 0; q < KY; q++) {
            float2 ov = sO[m*KY + q];
            acc[q].x += ov.x*e.x - ov.y*e.y;
            acc[q].y += ov.x*e.y + ov.y*e.x;
        }
    }
    float2* out = g_T + ((size_t)bo * HP + t) * KY;
    #pragma unroll
    for (int q = 0; q < KY; q++) out[q] = acc[q];
}

// ---------------- E: fused conv + inverse y-DFT; full-row blocks ----------------
#define HS2 296
#define WS 68
__global__ void __launch_bounds__(256) k_layer(const float* __restrict__ hin,
                                               float* __restrict__ hout,
                                               const float* __restrict__ conv_w,
                                               const float* __restrict__ conv_b,
                                               int l, int dogelu) {
    __shared__ __align__(16) float sH[32*HS2];
    __shared__ float sW[32*WS];
    __shared__ float scb[CC];
    int blk = blockIdx.x;
    int b = blk / HP, x = blk % HP;
    int t = threadIdx.x;

    for (int idx = t; idx < 32*72; idx += 256) {
        int r = idx / 72, c4 = (idx % 72) * 4;
        float4 v = *(const float4*)(hin + (size_t)(b*CC + r)*PLANE + (size_t)x*HP + c4);
        *(float4*)(sH + r*HS2 + c4) = v;
    }
    for (int idx = t; idx < 32*56; idx += 256) {
        int o = idx / 56, c = idx % 56;
        float w;
        if (c < 32)
            w = conv_w[l*CC*CC + o*CC + c];
        else if (c < 44)
            w = g_T[((size_t)(b*CC + o)*HP + x)*KY + (c-32)].x;
        else
            w = -g_T[((size_t)(b*CC + o)*HP + x)*KY + (c-44)].y;
        sW[o*WS + c] = w;
    }
    if (t < CC) scb[t] = conv_b[l*CC + t];
    __syncthreads();

    int wid = t >> 5, lane = t & 31;
    int warp_m = wid & 1, warp_n = wid >> 1;
    int lr = lane >> 2, lc = lane & 3;

    float acc[9][4];
    #pragma unroll
    for (int nt = 0; nt < 9; nt++)
        #pragma unroll
        for (int j = 0; j < 4; j++) acc[nt][j] = 0.0f;

    int row0 = warp_m*16 + lr;

    #pragma unroll
    for (int kb = 0; kb < 4; kb++) {
        int kk = kb*8 + lc;
        float a0f = sW[row0*WS + kk];
        float a1f = sW[(row0+8)*WS + kk];
        float a2f = sW[row0*WS + kk + 4];
        float a3f = sW[(row0+8)*WS + kk + 4];
        unsigned ah0, al0, ah1, al1, ah2, al2, ah3, al3;
        tfsplit(a0f, ah0, al0); tfsplit(a1f, ah1, al1);
        tfsplit(a2f, ah2, al2); tfsplit(a3f, ah3, al3);
        #pragma unroll
        for (int nt = 0; nt < 9; nt++) {
            int nb = warp_n*72 + nt*8 + lr;
            float b0f = sH[kk*HS2 + nb];
            float b1f = sH[(kk+4)*HS2 + nb];
            unsigned bh0, bl0, bh1, bl1;
            tfsplit(b0f, bh0, bl0);
            tfsplit(b1f, bh1, bl1);
            mma_tf32(acc[nt], ah0, ah1, ah2, ah3, bl0, bl1);
            mma_tf32(acc[nt], al0, al1, al2, al3, bh0, bh1);
            mma_tf32(acc[nt], ah0, ah1, ah2, ah3, bh0, bh1);
        }
    }
    #pragma unroll
    for (int kb = 4; kb < 7; kb++) {
        int kk = kb*8 + lc;
        float a0f = sW[row0*WS + kk];
        float a1f = sW[(row0+8)*WS + kk];
        float a2f = sW[row0*WS + kk + 4];
        float a3f = sW[(row0+8)*WS + kk + 4];
        unsigned ah0, al0, ah1, al1, ah2, al2, ah3, al3;
        tfsplit(a0f, ah0, al0); tfsplit(a1f, ah1, al1);
        tfsplit(a2f, ah2, al2); tfsplit(a3f, ah3, al3);
        int q0 = kk - 32, q1 = kk - 28;
        const unsigned* t0h = (q0 < 12) ? (g_ICyh + q0*HP) : (g_ISyh + (q0-12)*HP);
        const unsigned* t0l = (q0 < 12) ? (g_ICyl + q0*HP) : (g_ISyl + (q0-12)*HP);
        const unsigned* t1h = (q1 < 12) ? (g_ICyh + q1*HP) : (g_ISyh + (q1-12)*HP);
        const unsigned* t1l = (q1 < 12) ? (g_ICyl + q1*HP) : (g_ISyl + (q1-12)*HP);
        #pragma unroll
        for (int nt = 0; nt < 9; nt++) {
            int y = warp_n*72 + nt*8 + lr;
            unsigned bh0 = __ldg(&t0h[y]);
            unsigned bl0 = __ldg(&t0l[y]);
            unsigned bh1 = __ldg(&t1h[y]);
            unsigned bl1 = __ldg(&t1l[y]);
            mma_tf32(acc[nt], ah0, ah1, ah2, ah3, bl0, bl1);
            mma_tf32(acc[nt], al0, al1, al2, al3, bh0, bh1);
            mma_tf32(acc[nt], ah0, ah1, ah2, ah3, bh0, bh1);
        }
    }

    int o0 = warp_m*16 + lr;
    ull b0p = dup2(scb[o0]), b1p = dup2(scb[o0 + 8]);
    float* base0 = hout + (size_t)(b*CC + o0)*PLANE + (size_t)x*HP;
    float* base1 = hout + (size_t)(b*CC + o0 + 8)*PLANE + (size_t)x*HP;
    #pragma unroll
    for (int nt = 0; nt < 9; nt++) {
        int y = warp_n*72 + nt*8 + 2*lc;
        ull a01 = f2add(pk(acc[nt][0], acc[nt][1]), b0p);
        ull a23 = f2add(pk(acc[nt][2], acc[nt][3]), b1p);
        if (dogelu) { a01 = gelu2(a01); a23 = gelu2(a23); }
        *(ull*)(base0 + y) = a01;
        *(ull*)(base1 + y) = a23;
    }
}

// ---------------- final MLP 32 -> 128 (gelu) -> 2 as tf32 MMA ----------------
#define SBS 136
__global__ void __launch_bounds__(256) k_mlp(const float* __restrict__ hin,
                                             const float* __restrict__ b1,
                                             const float* __restrict__ w2,
                                             const float* __restrict__ b2) {
    __shared__ __align__(16) float sB[32*SBS];
    __shared__ float sw2[256];
    __shared__ float sb1[128];
    __shared__ float sD[512];
    int t = threadIdx.x;
    int blk = blockIdx.x;
    int b = blk >> 8, ii = blk & 255;
    int yh = blockIdx.y;

    #pragma unroll
    for (int k = 0; k < 4; k++) {
        int idx = t + k*256;
        int row = idx >> 5, c4 = (idx & 31) * 4;
        float4 v = *(const float4*)(hin + (size_t)(b*CC + row)*PLANE + (size_t)ii*HP + yh*128 + c4);
        *(float4*)(sB + row*SBS + c4) = v;
    }
    if (t < 128) sb1[t] = b1[t];
    sw2[t] = w2[t];
    __syncthreads();

    int wid = t >> 5, lane = t & 31;
    int lr = lane >> 2, lc = lane & 3;
    int yg = wid & 3, hh = wid >> 2;
    int ybl = yg * 32;

    ull d2[8];
    #pragma unroll
    for (int i = 0; i < 8; i++) d2[i] = 0ull;

    #pragma unroll
    for (int mtp = 0; mtp < 2; mtp++) {
        int h0 = hh*64 + mtp*32;
        float acc[2][4][4];
        #pragma unroll
        for (int m2 = 0; m2 < 2; m2++) {
            float ba = sb1[h0 + m2*16 + lr];
            float bb = sb1[h0 + m2*16 + lr + 8];
            #pragma unroll
            for (int nt = 0; nt < 4; nt++) {
                acc[m2][nt][0] = ba; acc[m2][nt][1] = ba;
                acc[m2][nt][2] = bb; acc[m2][nt][3] = bb;
            }
        }
        #pragma unroll
        for (int kb = 0; kb < 4; kb++) {
            int kk = kb*8 + lc;
            unsigned bh[4][2], bl[4][2];
            #pragma unroll
            for (int nt = 0; nt < 4; nt++) {
                float b0f = sB[kk*SBS + ybl + nt*8 + lr];
                float b1f = sB[(kk+4)*SBS + ybl + nt*8 + lr];
                tfsplit(b0f, bh[nt][0], bl[nt][0]);
                tfsplit(b1f, bh[nt][1], bl[nt][1]);
            }
            #pragma unroll
            for (int m2 = 0; m2 < 2; m2++) {
                int hb = h0 + m2*16;
                uint2 a0 = __ldg(&g_W1sp[(hb+lr)*32 + kk]);
                uint2 a1 = __ldg(&g_W1sp[(hb+lr+8)*32 + kk]);
                uint2 a2 = __ldg(&g_W1sp[(hb+lr)*32 + kk + 4]);
                uint2 a3 = __ldg(&g_W1sp[(hb+lr+8)*32 + kk + 4]);
                #pragma unroll
                for (int nt = 0; nt < 4; nt++) {
                    mma_tf32(acc[m2][nt], a0.x, a1.x, a2.x, a3.x, bl[nt][0], bl[nt][1]);
                    mma_tf32(acc[m2][nt], a0.y, a1.y, a2.y, a3.y, bh[nt][0], bh[nt][1]);
                    mma_tf32(acc[m2][nt], a0.x, a1.x, a2.x, a3.x, bh[nt][0], bh[nt][1]);
                }
            }
        }
        #pragma unroll
        for (int m2 = 0; m2 < 2; m2++) {
            int ha = h0 + m2*16 + lr, hb2 = ha + 8;
            ull w2a0 = dup2(sw2[ha]),  w2a1 = dup2(sw2[128 + ha]);
            ull w2b0 = dup2(sw2[hb2]), w2b1 = dup2(sw2[128 + hb2]);
            #pragma unroll
            for (int nt = 0; nt < 4; nt++) {
                ull g01 = gelu2(pk(acc[m2][nt][0], acc[m2][nt][1]));
                ull g23 = gelu2(pk(acc[m2][nt][2], acc[m2][nt][3]));
                d2[nt]     = f2fma(w2a0, g01, d2[nt]);
                d2[nt]     = f2fma(w2b0, g23, d2[nt]);
                d2[4 + nt] = f2fma(w2a1, g01, d2[4 + nt]);
                d2[4 + nt] = f2fma(w2b1, g23, d2[4 + nt]);
            }
        }
    }

    float d[16];
    #pragma unroll
    for (int nt = 0; nt < 4; nt++) {
        upk(d[nt*2], d[nt*2+1], d2[nt]);
        upk(d[8 + nt*2], d[8 + nt*2 + 1], d2[4 + nt]);
    }

    #pragma unroll
    for (int i = 0; i < 16; i++) {
        d[i] += __shfl_xor_sync(0xffffffffu, d[i], 4);
        d[i] += __shfl_xor_sync(0xffffffffu, d[i], 8);
        d[i] += __shfl_xor_sync(0xffffffffu, d[i], 16);
    }
    if (lr == 0) {
        #pragma unroll
        for (int i = 0; i < 16; i++) sD[wid*64 + lc*16 + i] = d[i];
    }
    __syncthreads();
    {
        int j = t & 1, yl = t >> 1;
        int yg2 = yl >> 5, cc2 = yl & 31;
        int nt = cc2 >> 3, rem = cc2 & 7, lc2 = rem >> 1, c01 = rem & 1;
        int k = j*8 + nt*2 + c01;
        float val = sD[yg2*64 + lc2*16 + k] + sD[(4+yg2)*64 + lc2*16 + k] + __ldg(&b2[j]);
        int p = ii*SS + yh*128 + yl;
        g_tmp[(size_t)(b*2 + j)*(SS*SS) + p] = val;
    }
}

// ---------------- output permutation ----------------
__global__ void k_scatter(const int* __restrict__ v2d, float* __restrict__ out) {
    int idx = blockIdx.x * blockDim.x + threadIdx.x;
    if (idx >= BB*SS*SS) return;
    int b = idx >> 16, n = idx & 65535;
    int p = v2d[n];
    float v0 = g_tmp[(size_t)(b*2    ) * SS*SS + p];
    float v1 = g_tmp[(size_t)(b*2 + 1) * SS*SS + p];
    reinterpret_cast<float2*>(out)[idx] = make_float2(v0, v1);
}

// ---------------- launch ----------------
extern "C" void kernel_launch(void* const* d_in, const int* in_sizes, int n_in,
                              void* d_out, int out_size) {
    const float* x    = (const float*)d_in[0];
    const int*   d2v  = (const int*)  d_in[1];
    const int*   v2d  = (const int*)  d_in[2];
    const float* fc0w = (const float*)d_in[3];
    const float* fc0b = (const float*)d_in[4];
    const float* w1r  = (const float*)d_in[5];
    const float* w1i  = (const float*)d_in[6];
    const float* w2r  = (const float*)d_in[7];
    const float* w2i  = (const float*)d_in[8];
    const float* cw   = (const float*)d_in[9];
    const float* cb   = (const float*)d_in[10];
    const float* mw1  = (const float*)d_in[11];
    const float* mb1  = (const float*)d_in[12];
    const float* mw2  = (const float*)d_in[13];
    const float* mb2  = (const float*)d_in[14];

    float *h0, *h1;
    cudaGetSymbolAddress((void**)&h0, g_h0);
    cudaGetSymbolAddress((void**)&h1, g_h1);

    k_basis<<<(MM*HP + 255)/256, 256>>>();
    k_transw<<<(NLAY*MM*KY*CC*CC + 255)/256, 256>>>(w1r, w1i, w2r, w2i, mw1);
    k_embed<<<(BB*PLANE + 255)/256, 256>>>(x, d2v, fc0w, fc0b, h0);

    float* cur = h0;
    float* nxt = h1;
    for (int l = 0; l < NLAY; l++) {
        k_ydft<<<dim3(BB*CC, 3), 192>>>(cur);
        k_xdft<<<BB*CC, 576>>>();
        k_mixix<<<BB*CC, 288>>>(l);
        k_layer<<<BB*HP, 256>>>(cur, nxt, cw, cb, l, (l < NLAY-1) ? 1 : 0);
        float* tp = cur; cur = nxt; nxt = tp;
    }
    k_mlp<<<dim3(BB*SS, 2), 256>>>(cur, mb1, mw2, mb2);
    k_scatter<<<(BB*SS*SS + 255)/256, 256>>>(v2d, (float*)d_out);
}

// round 17
// speedup vs baseline: 1.0660x; 1.0121x over previous
#include <cuda_runtime.h>
#include <math.h>

#define BB 8
#define CC 32
#define SS 256
#define HP 288
#define KY 12
#define MM 24
#define NLAY 4
#define PLANE (HP*HP)

typedef unsigned long long ull;

// ---------------- packed f32x2 helpers ----------------
__device__ __forceinline__ ull pk(float lo, float hi) {
    ull r; asm("mov.b64 %0,{%1,%2};" : "=l"(r) : "f"(lo), "f"(hi)); return r;
}
__device__ __forceinline__ ull dup2(float v) { return pk(v, v); }
__device__ __forceinline__ void upk(float& lo, float& hi, ull v) {
    asm("mov.b64 {%0,%1},%2;" : "=f"(lo), "=f"(hi) : "l"(v));
}
__device__ __forceinline__ ull f2fma(ull a, ull b, ull c) {
    ull d; asm("fma.rn.f32x2 %0,%1,%2,%3;" : "=l"(d) : "l"(a), "l"(b), "l"(c)); return d;
}
__device__ __forceinline__ ull f2add(ull a, ull b) {
    ull d; asm("add.rn.f32x2 %0,%1,%2;" : "=l"(d) : "l"(a), "l"(b)); return d;
}
__device__ __forceinline__ ull f2mul(ull a, ull b) {
    ull d; asm("mul.rn.f32x2 %0,%1,%2;" : "=l"(d) : "l"(a), "l"(b)); return d;
}

// ---------------- tf32 mma helpers ----------------
__device__ __forceinline__ unsigned f2tf(float x) {
    unsigned r; asm("cvt.rna.tf32.f32 %0,%1;" : "=r"(r) : "f"(x)); return r;
}
__device__ __forceinline__ void tfsplit(float x, unsigned& hi, unsigned& lo) {
    hi = f2tf(x);
    float res = x - __uint_as_float(hi);
    lo = f2tf(res);
}
__device__ __forceinline__ void mma_tf32(float c[4],
    unsigned a0, unsigned a1, unsigned a2, unsigned a3,
    unsigned b0, unsigned b1) {
    asm volatile(
        "mma.sync.aligned.m16n8k8.row.col.f32.tf32.tf32.f32 "
        "{%0,%1,%2,%3},{%4,%5,%6,%7},{%8,%9},{%0,%1,%2,%3};"
        : "+f"(c[0]), "+f"(c[1]), "+f"(c[2]), "+f"(c[3])
        : "r"(a0), "r"(a1), "r"(a2), "r"(a3), "r"(b0), "r"(b1));
}

// ---------------- cp.async ----------------
__device__ __forceinline__ void cpasync16(void* smem, const void* g) {
    unsigned s = (unsigned)__cvta_generic_to_shared(smem);
    asm volatile("cp.async.ca.shared.global [%0], [%1], 16;" :: "r"(s), "l"(g));
}

// ---------------- device scratch ----------------
__device__ float  g_h0[BB*CC*PLANE];
__device__ float  g_h1[BB*CC*PLANE];
__device__ float2 g_G [BB*CC*HP*KY];
__device__ float2 g_F [BB*CC*MM*KY];
__device__ float2 g_T [BB*CC*HP*KY];
__device__ float2 g_WT[(size_t)NLAY*CC*CC*MM*KY];   // [l][i][o][mk] = {wr, wi}
__device__ uint2  g_EySp[HP*24];     // [y][2ky re/im] {hi,lo}
__device__ unsigned g_ICyh[KY*HP];
__device__ unsigned g_ICyl[KY*HP];
__device__ unsigned g_ISyh[KY*HP];
__device__ unsigned g_ISyl[KY*HP];
__device__ uint2  g_W1sp[128*32];
__device__ float2 g_Ex [MM*HP];
__device__ float2 g_Exi[MM*HP];
__device__ float  g_tmp[BB*2*SS*SS];

// Packed pair gelu: A&S 7.1.26 erf (4-term), f32x2, branchless.
__device__ __forceinline__ ull gelu2(ull x2) {
    ull z = f2mul(x2, dup2(0.70710678118654752440f));
    ull az; asm("and.b64 %0,%1,%2;" : "=l"(az) : "l"(z), "l"(0x7FFFFFFF7FFFFFFFULL));
    ull den = f2fma(az, dup2(0.3275911f), dup2(1.0f));
    float d0, d1; upk(d0, d1, den);
    ull tt = pk(__fdividef(1.0f, d0), __fdividef(1.0f, d1));
    ull p = f2fma(tt, dup2(1.061405429f), dup2(-1.453152027f));
    p = f2fma(p, tt, dup2(1.421413741f));
    p = f2fma(p, tt, dup2(-0.284496736f));
    p = f2fma(p, tt, dup2(0.254829592f));
    p = f2mul(p, tt);
    ull m  = f2mul(z, z);
    ull ea = f2mul(m, dup2(-1.4426950408889634f));
    float e0a, e1a; upk(e0a, e1a, ea);
    float e0, e1;
    asm("ex2.approx.f32 %0,%1;" : "=f"(e0) : "f"(e0a));
    asm("ex2.approx.f32 %0,%1;" : "=f"(e1) : "f"(e1a));
    ull e = pk(e0, e1);
    ull np; asm("xor.b64 %0,%1,%2;" : "=l"(np) : "l"(p), "l"(0x8000000080000000ULL));
    ull w = f2fma(np, e, dup2(1.0f));
    ull ws; asm("and.b64 %0,%1,%2;" : "=l"(ws) : "l"(w),  "l"(0x7FFFFFFF7FFFFFFFULL));
    ull xs; asm("and.b64 %0,%1,%2;" : "=l"(xs) : "l"(x2), "l"(0x8000000080000000ULL));
    ull wc; asm("or.b64 %0,%1,%2;"  : "=l"(wc) : "l"(ws), "l"(xs));
    ull s = f2fma(wc, dup2(0.5f), dup2(0.5f));
    return f2mul(x2, s);
}

// ---------------- basis tables ----------------
__global__ void k_basis() {
    int idx = blockIdx.x * blockDim.x + threadIdx.x;
    if (idx < KY*HP) {
        int ky = idx / HP, y = idx % HP;
        int r = (ky * y) % HP;
        float a = 6.28318530717958647692f * (float)r / (float)HP;
        float c = cosf(a), s = sinf(a);
        unsigned hh, ll;
        tfsplit(c, hh, ll);
        g_EySp[y*24 + 2*ky] = make_uint2(hh, ll);
        tfsplit(-s, hh, ll);
        g_EySp[y*24 + 2*ky + 1] = make_uint2(hh, ll);
        float al = (ky == 0) ? 1.0f : 2.0f;
        float inv = 1.0f / ((float)HP * (float)HP);
        tfsplit(al*inv*c, hh, ll);
        g_ICyh[idx] = hh; g_ICyl[idx] = ll;
        tfsplit(al*inv*s, hh, ll);
        g_ISyh[idx] = hh; g_ISyl[idx] = ll;
    }
    if (idx < MM*HP) {
        int m = idx / HP, xx = idx % HP;
        int kx = (m < KY) ? m : (264 + m);
        int r = (kx * xx) % HP;
        float a = 6.28318530717958647692f * (float)r / (float)HP;
        float c = cosf(a), s = sinf(a);
        g_Ex[idx]  = make_float2(c, -s);
        g_Exi[idx] = make_float2(c,  s);
    }
}

// ---------------- weight transpose + w1 split ----------------
__global__ void k_transw(const float* __restrict__ w1r, const float* __restrict__ w1i,
                         const float* __restrict__ w2r, const float* __restrict__ w2i,
                         const float* __restrict__ mw1) {
    int idx = blockIdx.x * blockDim.x + threadIdx.x;
    if (idx < 128*32) {
        unsigned hh, ll;
        tfsplit(mw1[idx], hh, ll);
        g_W1sp[idx] = make_uint2(hh, ll);
    }
    if (idx >= NLAY*MM*KY*CC*CC) return;
    int o  = idx & 31;
    int i  = (idx >> 5) & 31;
    int ky = (idx >> 10) % KY;
    int rest = idx / (1024 * KY);
    int m = rest % MM;
    int l = rest / MM;
    const float *sr, *si;
    int src;
    if (m < KY) {
        src = (((l*CC + i)*CC + o)*12 + m)*12 + ky;
        sr = w1r; si = w1i;
    } else {
        src = (((l*CC + i)*CC + o)*12 + (m - 12))*12 + ky;
        sr = w2r; si = w2i;
    }
    int mk = m*KY + ky;
    g_WT[(((size_t)(l*CC + i) * CC + o) * (MM*KY)) + mk] = make_float2(sr[src], si[src]);
}

// ---------------- stage 0: embed ----------------
__global__ void k_embed(const float* __restrict__ xin, const int* __restrict__ d2v,
                        const float* __restrict__ fw, const float* __restrict__ fb,
                        float* __restrict__ hout) {
    int idx = blockIdx.x * blockDim.x + threadIdx.x;
    if (idx >= BB*PLANE) return;
    int b = idx / PLANE;
    int rem = idx % PLANE;
    int i = rem / HP, j = rem % HP;
    float* hp = hout + (size_t)b * CC * PLANE + rem;
    if (i < SS && j < SS) {
        float v  = xin[b*SS*SS + d2v[i*SS + j]];
        float gi = (float)i * (1.0f/255.0f);
        float gj = (float)j * (1.0f/255.0f);
        #pragma unroll
        for (int c = 0; c < CC; c++)
            hp[(size_t)c*PLANE] = fw[c*3]*v + fw[c*3+1]*gi + fw[c*3+2]*gj + fb[c];
    } else {
        #pragma unroll
        for (int c = 0; c < CC; c++) hp[(size_t)c*PLANE] = 0.0f;
    }
}

// ---------------- A: truncated y-DFT, tf32 MMA, smem-staged split twiddles ----------------
// grid (B*C, 3), block 192 = 6 warps x 16 rows. K in 9 chunks of 32, double-buffered.
#define AS 36
__global__ void __launch_bounds__(192) k_ydft(const float* __restrict__ h) {
    __shared__ __align__(16) float sA[2][96*AS];
    __shared__ __align__(16) uint2 sE[2][32*24];
    int t = threadIdx.x;
    int bc = blockIdx.x;
    const float* A = h + (size_t)bc * PLANE + (size_t)(blockIdx.y * 96) * HP;

    #pragma unroll
    for (int k = 0; k < 4; k++) {
        int idx = t + k*192;
        int row = idx >> 3, c4 = (idx & 7) * 4;
        cpasync16(&sA[0][row*AS + c4], A + (size_t)row*HP + c4);
    }
    #pragma unroll
    for (int k = 0; k < 2; k++) {
        int idx = t + k*192;
        cpasync16(&sE[0][idx*2], g_EySp + idx*2);
    }
    asm volatile("cp.async.commit_group;");

    int wid = t >> 5, lane = t & 31;
    int lr = lane >> 2, lc = lane & 3;

    float acc[3][4];
    #pragma unroll
    for (int nt = 0; nt < 3; nt++)
        #pragma unroll
        for (int j = 0; j < 4; j++) acc[nt][j] = 0.0f;

    for (int c = 0; c < 9; c++) {
        if (c + 1 < 9) {
            const float* src = A + (c+1)*32;
            #pragma unroll
            for (int k = 0; k < 4; k++) {
                int idx = t + k*192;
                int row = idx >> 3, c4 = (idx & 7) * 4;
                cpasync16(&sA[(c+1)&1][row*AS + c4], src + (size_t)row*HP + c4);
            }
            const uint2* esrc = g_EySp + (c+1)*32*24;
            #pragma unroll
            for (int k = 0; k < 2; k++) {
                int idx = t + k*192;
                cpasync16(&sE[(c+1)&1][idx*2], esrc + idx*2);
            }
            asm volatile("cp.async.commit_group;");
            asm volatile("cp.async.wait_group 1;");
        } else {
            asm volatile("cp.async.wait_group 0;");
        }
        __syncthreads();

        const float* a = sA[c&1] + wid*16*AS;
        const uint2* e = sE[c&1];
        #pragma unroll
        for (int kb = 0; kb < 4; kb++) {
            int kk = kb*8 + lc;
            float a0f = a[lr*AS + kk];
            float a1f = a[(lr+8)*AS + kk];
            float a2f = a[lr*AS + kk + 4];
            float a3f = a[(lr+8)*AS + kk + 4];
            unsigned ah0, al0, ah1, al1, ah2, al2, ah3, al3;
            tfsplit(a0f, ah0, al0); tfsplit(a1f, ah1, al1);
            tfsplit(a2f, ah2, al2); tfsplit(a3f, ah3, al3);
            #pragma unroll
            for (int nt = 0; nt < 3; nt++) {
                uint2 b0 = e[kk*24 + nt*8 + lr];
                uint2 b1 = e[(kk+4)*24 + nt*8 + lr];
                mma_tf32(acc[nt], ah0, ah1, ah2, ah3, b0.y, b1.y);
                mma_tf32(acc[nt], al0, al1, al2, al3, b0.x, b1.x);
                mma_tf32(acc[nt], ah0, ah1, ah2, ah3, b0.x, b1.x);
            }
        }
        __syncthreads();
    }

    int x0 = blockIdx.y * 96 + wid * 16;
    float2* out0 = g_G + ((size_t)bc * HP + x0 + lr) * KY;
    float2* out1 = out0 + 8 * KY;
    #pragma unroll
    for (int nt = 0; nt < 3; nt++) {
        out0[nt*4 + lc] = make_float2(acc[nt][0], acc[nt][1]);
        out1[nt*4 + lc] = make_float2(acc[nt][2], acc[nt][3]);
    }
}

// ---------------- B: x-DFT onto 24 modes; 2-way x-split for latency ----------------
__global__ void __launch_bounds__(576) k_xdft() {
    __shared__ float2 sG[HP*KY];
    __shared__ float2 sP[288];
    int bc = blockIdx.x, t = threadIdx.x;
    const float2* Gp = g_G + (size_t)bc * HP * KY;
    for (int i = t; i < HP*KY; i += 576) sG[i] = Gp[i];
    __syncthreads();
    int half = t / 288, mk = t % 288;
    int m = mk / KY, ky = mk % KY;
    float accx = 0.0f, accy = 0.0f;
    const float2* ex = g_Ex + m * HP + half * 144;
    const float2* gp = sG + (size_t)(half * 144) * KY + ky;
    #pragma unroll 4
    for (int x = 0; x < 144; x++) {
        float2 g = gp[x*KY];
        float2 e = ex[x];
        accx += g.x*e.x - g.y*e.y;
        accy += g.x*e.y + g.y*e.x;
    }
    if (half == 1) sP[mk] = make_float2(accx, accy);
    __syncthreads();
    if (half == 0) {
        float2 p = sP[mk];
        g_F[(size_t)bc * MM * KY + mk] = make_float2(accx + p.x, accy + p.y);
    }
}

// ---------------- C+D fused: channel mix + inverse x-DFT ----------------
__global__ void __launch_bounds__(288) k_mixix(int l) {
    __shared__ float2 sO[MM*KY];
    int bo = blockIdx.x;
    int b = bo >> 5, o = bo & 31;
    int t = threadIdx.x;

    {
        const float2* wp = g_WT + ((size_t)(l*CC) * CC + o) * (MM*KY) + t;
        const float2* Fp = g_F + (size_t)b * CC * (MM*KY) + t;
        float accr = 0.0f, acci = 0.0f;
        #pragma unroll 8
        for (int i = 0; i < CC; i++) {
            float2 w = wp[(size_t)i * CC * (MM*KY)];
            float2 f = Fp[(size_t)i * (MM*KY)];
            accr += f.x*w.x - f.y*w.y;
            acci += f.x*w.y + f.y*w.x;
        }
        sO[t] = make_float2(accr, acci);
    }
    __syncthreads();

    float2 acc[KY];
    #pragma unroll
    for (int q = 0; q < KY; q++) acc[q] = make_float2(0.0f, 0.0f);
    #pragma unroll 4
    for (int m = 0; m < MM; m++) {
        float2 e = g_Exi[m*HP + t];
        #pragma unroll
        for (int q = 0; q < KY; q++) {
            float2 ov = sO[m*KY + q];
            acc[q].x += ov.x*e.x - ov.y*e.y;
            acc[q].y += ov.x*e.y + ov.y*e.x;
        }
    }
    float2* out = g_T + ((size_t)bo * HP + t) * KY;
    #pragma unroll
    for (int q = 0; q < KY; q++) out[q] = acc[q];
}

// ---------------- E: fused conv + inverse y-DFT; 3-pass y-tiling (96 cols) ----------------
#define HS3 104
#define WS 68
__global__ void __launch_bounds__(256) k_layer(const float* __restrict__ hin,
                                               float* __restrict__ hout,
                                               const float* __restrict__ conv_w,
                                               const float* __restrict__ conv_b,
                                               int l, int dogelu) {
    __shared__ __align__(16) float sH[32*HS3];
    __shared__ float sW[32*WS];
    __shared__ float scb[CC];
    int blk = blockIdx.x;
    int b = blk / HP, x = blk % HP;
    int t = threadIdx.x;

    for (int idx = t; idx < 32*56; idx += 256) {
        int o = idx / 56, c = idx % 56;
        float w;
        if (c < 32)
            w = conv_w[l*CC*CC + o*CC + c];
        else if (c < 44)
            w = g_T[((size_t)(b*CC + o)*HP + x)*KY + (c-32)].x;
        else
            w = -g_T[((size_t)(b*CC + o)*HP + x)*KY + (c-44)].y;
        sW[o*WS + c] = w;
    }
    if (t < CC) scb[t] = conv_b[l*CC + t];

    int wid = t >> 5, lane = t & 31;
    int warp_m = wid & 1, warp_n = wid >> 1;
    int lr = lane >> 2, lc = lane & 3;
    int row0 = warp_m*16 + lr;
    int o0 = warp_m*16 + lr;
    ull b0p, b1p;
    float* base0;
    float* base1;

    #pragma unroll 1
    for (int p = 0; p < 3; p++) {
        if (p) __syncthreads();     // prior pass reads of sH complete
        int y0 = p * 96;
        // load 96-col slab of h
        for (int idx = t; idx < 32*24; idx += 256) {
            int r = idx / 24, c4 = (idx % 24) * 4;
            float4 v = *(const float4*)(hin + (size_t)(b*CC + r)*PLANE + (size_t)x*HP + y0 + c4);
            *(float4*)(sH + r*HS3 + c4) = v;
        }
        __syncthreads();

        float acc[3][4];
        #pragma unroll
        for (int nt = 0; nt < 3; nt++)
            #pragma unroll
            for (int j = 0; j < 4; j++) acc[nt][j] = 0.0f;

        #pragma unroll
        for (int kb = 0; kb < 4; kb++) {
            int kk = kb*8 + lc;
            float a0f = sW[row0*WS + kk];
            float a1f = sW[(row0+8)*WS + kk];
            float a2f = sW[row0*WS + kk + 4];
            float a3f = sW[(row0+8)*WS + kk + 4];
            unsigned ah0, al0, ah1, al1, ah2, al2, ah3, al3;
            tfsplit(a0f, ah0, al0); tfsplit(a1f, ah1, al1);
            tfsplit(a2f, ah2, al2); tfsplit(a3f, ah3, al3);
            #pragma unroll
            for (int nt = 0; nt < 3; nt++) {
                int nb = warp_n*24 + nt*8 + lr;
                float b0f = sH[kk*HS3 + nb];
                float b1f = sH[(kk+4)*HS3 + nb];
                unsigned bh0, bl0, bh1, bl1;
                tfsplit(b0f, bh0, bl0);
                tfsplit(b1f, bh1, bl1);
                mma_tf32(acc[nt], ah0, ah1, ah2, ah3, bl0, bl1);
                mma_tf32(acc[nt], al0, al1, al2, al3, bh0, bh1);
                mma_tf32(acc[nt], ah0, ah1, ah2, ah3, bh0, bh1);
            }
        }
        #pragma unroll
        for (int kb = 4; kb < 7; kb++) {
            int kk = kb*8 + lc;
            float a0f = sW[row0*WS + kk];
            float a1f = sW[(row0+8)*WS + kk];
            float a2f = sW[row0*WS + kk + 4];
            float a3f = sW[(row0+8)*WS + kk + 4];
            unsigned ah0, al0, ah1, al1, ah2, al2, ah3, al3;
            tfsplit(a0f, ah0, al0); tfsplit(a1f, ah1, al1);
            tfsplit(a2f, ah2, al2); tfsplit(a3f, ah3, al3);
            int q0 = kk - 32, q1 = kk - 28;
            const unsigned* t0h = (q0 < 12) ? (g_ICyh + q0*HP) : (g_ISyh + (q0-12)*HP);
            const unsigned* t0l = (q0 < 12) ? (g_ICyl + q0*HP) : (g_ISyl + (q0-12)*HP);
            const unsigned* t1h = (q1 < 12) ? (g_ICyh + q1*HP) : (g_ISyh + (q1-12)*HP);
            const unsigned* t1l = (q1 < 12) ? (g_ICyl + q1*HP) : (g_ISyl + (q1-12)*HP);
            #pragma unroll
            for (int nt = 0; nt < 3; nt++) {
                int y = y0 + warp_n*24 + nt*8 + lr;
                unsigned bh0 = __ldg(&t0h[y]);
                unsigned bl0 = __ldg(&t0l[y]);
                unsigned bh1 = __ldg(&t1h[y]);
                unsigned bl1 = __ldg(&t1l[y]);
                mma_tf32(acc[nt], ah0, ah1, ah2, ah3, bl0, bl1);
                mma_tf32(acc[nt], al0, al1, al2, al3, bh0, bh1);
                mma_tf32(acc[nt], ah0, ah1, ah2, ah3, bh0, bh1);
            }
        }

        b0p = dup2(scb[o0]); b1p = dup2(scb[o0 + 8]);
        base0 = hout + (size_t)(b*CC + o0)*PLANE + (size_t)x*HP;
        base1 = hout + (size_t)(b*CC + o0 + 8)*PLANE + (size_t)x*HP;
        #pragma unroll
        for (int nt = 0; nt < 3; nt++) {
            int y = y0 + warp_n*24 + nt*8 + 2*lc;
            ull a01 = f2add(pk(acc[nt][0], acc[nt][1]), b0p);
            ull a23 = f2add(pk(acc[nt][2], acc[nt][3]), b1p);
            if (dogelu) { a01 = gelu2(a01); a23 = gelu2(a23); }
            *(ull*)(base0 + y) = a01;
            *(ull*)(base1 + y) = a23;
        }
    }
}

// ---------------- final MLP 32 -> 128 (gelu) -> 2 as tf32 MMA ----------------
#define SBS 136
__global__ void __launch_bounds__(256) k_mlp(const float* __restrict__ hin,
                                             const float* __restrict__ b1,
                                             const float* __restrict__ w2,
                                             const float* __restrict__ b2) {
    __shared__ __align__(16) float sB[32*SBS];
    __shared__ float sw2[256];
    __shared__ float sb1[128];
    __shared__ float sD[512];
    int t = threadIdx.x;
    int blk = blockIdx.x;
    int b = blk >> 8, ii = blk & 255;
    int yh = blockIdx.y;

    #pragma unroll
    for (int k = 0; k < 4; k++) {
        int idx = t + k*256;
        int row = idx >> 5, c4 = (idx & 31) * 4;
        float4 v = *(const float4*)(hin + (size_t)(b*CC + row)*PLANE + (size_t)ii*HP + yh*128 + c4);
        *(float4*)(sB + row*SBS + c4) = v;
    }
    if (t < 128) sb1[t] = b1[t];
    sw2[t] = w2[t];
    __syncthreads();

    int wid = t >> 5, lane = t & 31;
    int lr = lane >> 2, lc = lane & 3;
    int yg = wid & 3, hh = wid >> 2;
    int ybl = yg * 32;

    ull d2[8];
    #pragma unroll
    for (int i = 0; i < 8; i++) d2[i] = 0ull;

    #pragma unroll
    for (int mtp = 0; mtp < 2; mtp++) {
        int h0 = hh*64 + mtp*32;
        float acc[2][4][4];
        #pragma unroll
        for (int m2 = 0; m2 < 2; m2++) {
            float ba = sb1[h0 + m2*16 + lr];
            float bb = sb1[h0 + m2*16 + lr + 8];
            #pragma unroll
            for (int nt = 0; nt < 4; nt++) {
                acc[m2][nt][0] = ba; acc[m2][nt][1] = ba;
                acc[m2][nt][2] = bb; acc[m2][nt][3] = bb;
            }
        }
        #pragma unroll
        for (int kb = 0; kb < 4; kb++) {
            int kk = kb*8 + lc;
            unsigned bh[4][2], bl[4][2];
            #pragma unroll
            for (int nt = 0; nt < 4; nt++) {
                float b0f = sB[kk*SBS + ybl + nt*8 + lr];
                float b1f = sB[(kk+4)*SBS + ybl + nt*8 + lr];
                tfsplit(b0f, bh[nt][0], bl[nt][0]);
                tfsplit(b1f, bh[nt][1], bl[nt][1]);
            }
            #pragma unroll
            for (int m2 = 0; m2 < 2; m2++) {
                int hb = h0 + m2*16;
                uint2 a0 = __ldg(&g_W1sp[(hb+lr)*32 + kk]);
                uint2 a1 = __ldg(&g_W1sp[(hb+lr+8)*32 + kk]);
                uint2 a2 = __ldg(&g_W1sp[(hb+lr)*32 + kk + 4]);
                uint2 a3 = __ldg(&g_W1sp[(hb+lr+8)*32 + kk + 4]);
                #pragma unroll
                for (int nt = 0; nt < 4; nt++) {
                    mma_tf32(acc[m2][nt], a0.x, a1.x, a2.x, a3.x, bl[nt][0], bl[nt][1]);
                    mma_tf32(acc[m2][nt], a0.y, a1.y, a2.y, a3.y, bh[nt][0], bh[nt][1]);
                    mma_tf32(acc[m2][nt], a0.x, a1.x, a2.x, a3.x, bh[nt][0], bh[nt][1]);
                }
            }
        }
        #pragma unroll
        for (int m2 = 0; m2 < 2; m2++) {
            int ha = h0 + m2*16 + lr, hb2 = ha + 8;
            ull w2a0 = dup2(sw2[ha]),  w2a1 = dup2(sw2[128 + ha]);
            ull w2b0 = dup2(sw2[hb2]), w2b1 = dup2(sw2[128 + hb2]);
            #pragma unroll
            for (int nt = 0; nt < 4; nt++) {
                ull g01 = gelu2(pk(acc[m2][nt][0], acc[m2][nt][1]));
                ull g23 = gelu2(pk(acc[m2][nt][2], acc[m2][nt][3]));
                d2[nt]     = f2fma(w2a0, g01, d2[nt]);
                d2[nt]     = f2fma(w2b0, g23, d2[nt]);
                d2[4 + nt] = f2fma(w2a1, g01, d2[4 + nt]);
                d2[4 + nt] = f2fma(w2b1, g23, d2[4 + nt]);
            }
        }
    }

    float d[16];
    #pragma unroll
    for (int nt = 0; nt < 4; nt++) {
        upk(d[nt*2], d[nt*2+1], d2[nt]);
        upk(d[8 + nt*2], d[8 + nt*2 + 1], d2[4 + nt]);
    }

    #pragma unroll
    for (int i = 0; i < 16; i++) {
        d[i] += __shfl_xor_sync(0xffffffffu, d[i], 4);
        d[i] += __shfl_xor_sync(0xffffffffu, d[i], 8);
        d[i] += __shfl_xor_sync(0xffffffffu, d[i], 16);
    }
    if (lr == 0) {
        #pragma unroll
        for (int i = 0; i < 16; i++) sD[wid*64 + lc*16 + i] = d[i];
    }
    __syncthreads();
    {
        int j = t & 1, yl = t >> 1;
        int yg2 = yl >> 5, cc2 = yl & 31;
        int nt = cc2 >> 3, rem = cc2 & 7, lc2 = rem >> 1, c01 = rem & 1;
        int k = j*8 + nt*2 + c01;
        float val = sD[yg2*64 + lc2*16 + k] + sD[(4+yg2)*64 + lc2*16 + k] + __ldg(&b2[j]);
        int p = ii*SS + yh*128 + yl;
        g_tmp[(size_t)(b*2 + j)*(SS*SS) + p] = val;
    }
}

// ---------------- output permutation ----------------
__global__ void k_scatter(const int* __restrict__ v2d, float* __restrict__ out) {
    int idx = blockIdx.x * blockDim.x + threadIdx.x;
    if (idx >= BB*SS*SS) return;
    int b = idx >> 16, n = idx & 65535;
    int p = v2d[n];
    float v0 = g_tmp[(size_t)(b*2    ) * SS*SS + p];
    float v1 = g_tmp[(size_t)(b*2 + 1) * SS*SS + p];
    reinterpret_cast<float2*>(out)[idx] = make_float2(v0, v1);
}

// ---------------- launch ----------------
extern "C" void kernel_launch(void* const* d_in, const int* in_sizes, int n_in,
                              void* d_out, int out_size) {
    const float* x    = (const float*)d_in[0];
    const int*   d2v  = (const int*)  d_in[1];
    const int*   v2d  = (const int*)  d_in[2];
    const float* fc0w = (const float*)d_in[3];
    const float* fc0b = (const float*)d_in[4];
    const float* w1r  = (const float*)d_in[5];
    const float* w1i  = (const float*)d_in[6];
    const float* w2r  = (const float*)d_in[7];
    const float* w2i  = (const float*)d_in[8];
    const float* cw   = (const float*)d_in[9];
    const float* cb   = (const float*)d_in[10];
    const float* mw1  = (const float*)d_in[11];
    const float* mb1  = (const float*)d_in[12];
    const float* mw2  = (const float*)d_in[13];
    const float* mb2  = (const float*)d_in[14];

    float *h0, *h1;
    cudaGetSymbolAddress((void**)&h0, g_h0);
    cudaGetSymbolAddress((void**)&h1, g_h1);

    k_basis<<<(MM*HP + 255)/256, 256>>>();
    k_transw<<<(NLAY*MM*KY*CC*CC + 255)/256, 256>>>(w1r, w1i, w2r, w2i, mw1);
    k_embed<<<(BB*PLANE + 255)/256, 256>>>(x, d2v, fc0w, fc0b, h0);

    float* cur = h0;
    float* nxt = h1;
    for (int l = 0; l < NLAY; l++) {
        k_ydft<<<dim3(BB*CC, 3), 192>>>(cur);
        k_xdft<<<BB*CC, 576>>>();
        k_mixix<<<BB*CC, 288>>>(l);
        k_layer<<<BB*HP, 256>>>(cur, nxt, cw, cb, l, (l < NLAY-1) ? 1 : 0);
        float* tp = cur; cur = nxt; nxt = tp;
    }
    k_mlp<<<dim3(BB*SS, 2), 256>>>(cur, mb1, mw2, mb2);
    k_scatter<<<(BB*SS*SS + 255)/256, 256>>>(v2d, (float*)d_out);
}